// round 14
// baseline (speedup 1.0000x reference)
#include <cuda_runtime.h>
#include <math_constants.h>

// Problem constants
#define BQ    2
#define NQ    8192
#define KNN   16
#define FULL  0xffffffffu
#define TOTAL_EDGES ((double)(BQ) * (double)(NQ) * (double)(KNN))

// Grid
#define G     26
#define NC    (G * G * G)          // 17576 cells per batch
#define NCB   (2 * NC)
#define Hc    0.4f
#define INVH  2.5f
#define XMIN  (-5.2f)              // XMIN + G*Hc = +5.2 (out-of-range clamped inward)

// KNN kernel layout
#define WPB   8
#define KBLOCK 256
#define NBLK  ((BQ * NQ) / WPB)    // 2048 blocks, 1 query per warp

__device__ int    g_counts[NCB];
__device__ int    g_cursor[NCB];
__device__ int    g_starts[NCB];          // per-batch exclusive prefix of counts
__device__ float4 g_pts[BQ * NQ];         // (x, y, z, idx-as-float-bits), cell-ordered
__device__ float  g_partials[NBLK];

__device__ __forceinline__ int cell_of(float x) {
    int c = (int)floorf((x - XMIN) * INVH);
    return min(max(c, 0), G - 1);
}

// ---------------- build kernels ----------------
__global__ void zero_kernel()
{
    for (int i = blockIdx.x * blockDim.x + threadIdx.x; i < NCB;
         i += gridDim.x * blockDim.x) {
        g_counts[i] = 0;
        g_cursor[i] = 0;
    }
}

__global__ void count_kernel(const float* __restrict__ pr)
{
    int gid = blockIdx.x * blockDim.x + threadIdx.x;
    if (gid >= BQ * NQ) return;
    int b = gid >> 13;                // / NQ
    float x = pr[gid * 3 + 0];
    float y = pr[gid * 3 + 1];
    float z = pr[gid * 3 + 2];
    int cell = (cell_of(x) * G + cell_of(y)) * G + cell_of(z);
    atomicAdd(&g_counts[b * NC + cell], 1);
}

// Exclusive prefix sum per batch (blockIdx.x = batch). 1024 threads.
__global__ void scan_kernel()
{
    __shared__ int warpsum[32];
    __shared__ int carry_s;
    const int base = blockIdx.x * NC;
    const int tid  = threadIdx.x;
    const int wid  = tid >> 5;
    const int lane = tid & 31;
    if (tid == 0) carry_s = 0;
    __syncthreads();

    const int nchunk = (NC + 1023) / 1024;
    for (int c = 0; c < nchunk; ++c) {
        int i = c * 1024 + tid;
        int v = (i < NC) ? g_counts[base + i] : 0;
        // warp inclusive scan
        int x = v;
#pragma unroll
        for (int o = 1; o < 32; o <<= 1) {
            int t = __shfl_up_sync(FULL, x, o);
            if (lane >= o) x += t;
        }
        if (lane == 31) warpsum[wid] = x;
        __syncthreads();
        if (wid == 0) {
            int w = warpsum[lane];
#pragma unroll
            for (int o = 1; o < 32; o <<= 1) {
                int t = __shfl_up_sync(FULL, w, o);
                if (lane >= o) w += t;
            }
            warpsum[lane] = w;       // inclusive across warps
        }
        __syncthreads();
        int woff = (wid > 0) ? warpsum[wid - 1] : 0;
        if (i < NC) g_starts[base + i] = carry_s + woff + x - v;
        int total = warpsum[31];
        __syncthreads();
        if (tid == 0) carry_s += total;
        __syncthreads();
    }
}

__global__ void scatter_kernel(const float* __restrict__ pr)
{
    int gid = blockIdx.x * blockDim.x + threadIdx.x;
    if (gid >= BQ * NQ) return;
    int b = gid >> 13;
    int n = gid & (NQ - 1);
    float x = pr[gid * 3 + 0];
    float y = pr[gid * 3 + 1];
    float z = pr[gid * 3 + 2];
    int cell = (cell_of(x) * G + cell_of(y)) * G + cell_of(z);
    int pos  = b * NQ + g_starts[b * NC + cell] + atomicAdd(&g_cursor[b * NC + cell], 1);
    g_pts[pos] = make_float4(x, y, z, __int_as_float(n));
}

// ---------------- KNN + loss ----------------
// Lexicographic stable insert into warp-distributed sorted top-16:
// lane l<16 holds the (l+1)-th smallest (d2, idx) pair. Order-independent:
// the final 16-set is the unique lex-minimal set, matching top_k (ascending
// d2, ties by lower index) regardless of candidate processing order.
__device__ __forceinline__ void insert_lex(float v, int vi, int lane,
                                           float& kd, int& ki,
                                           float& thr, int& thri)
{
    const unsigned le = __ballot_sync(FULL,
        (lane < KNN) && ((kd < v) || (kd == v && ki < vi)));
    const int pos = __popc(le);      // pos==16 -> no-op (stale/duplicate-rank)
    const float kdu = __shfl_up_sync(FULL, kd, 1);
    const int   kiu = __shfl_up_sync(FULL, ki, 1);
    if (lane >= pos) {
        kd = (lane == pos) ? v  : kdu;
        ki = (lane == pos) ? vi : kiu;
    }
    thr  = __shfl_sync(FULL, kd, KNN - 1);
    thri = __shfl_sync(FULL, ki, KNN - 1);
}

__global__ __launch_bounds__(KBLOCK)
void knn_loss_kernel(const float* __restrict__ points_ref,
                     const float* __restrict__ points)
{
    __shared__ float wsum[WPB];
    const int tid  = threadIdx.x;
    const int wid  = tid >> 5;
    const int lane = tid & 31;
    const int qg   = blockIdx.x * WPB + wid;      // global query id
    const int b    = qg >> 13;
    const int qn   = qg & (NQ - 1);

    const float* __restrict__ pr = points_ref + (size_t)b * NQ * 3;
    const float* __restrict__ pp = points     + (size_t)b * NQ * 3;
    const float4* __restrict__ P = g_pts + (size_t)b * NQ;
    const int* __restrict__ S = g_starts + b * NC;
    const int* __restrict__ C = g_counts + b * NC;

    const float qx  = pr[qn * 3 + 0];
    const float qy  = pr[qn * 3 + 1];
    const float qz  = pr[qn * 3 + 2];
    const float sqn = qx * qx + qy * qy + qz * qz;

    const int ccx = cell_of(qx), ccy = cell_of(qy), ccz = cell_of(qz);

    float kd; int ki; float thr; int thri;

    for (int ring = 1;; ++ring) {
        const int x0 = max(ccx - ring, 0), x1 = min(ccx + ring, G - 1);
        const int y0 = max(ccy - ring, 0), y1 = min(ccy + ring, G - 1);
        const int z0 = max(ccz - ring, 0), z1 = min(ccz + ring, G - 1);

        // fresh exact scan of the whole region
        kd = CUDART_INF_F; ki = 0x7fffffff;
        thr = CUDART_INF_F; thri = (int)0x80000000;   // INT_MIN: no eq-admit vs INF

        for (int cx = x0; cx <= x1; ++cx) {
            for (int cy = y0; cy <= y1; ++cy) {
                const int rowbase = (cx * G + cy) * G;
                const int rs = S[rowbase + z0];
                const int re = S[rowbase + z1] + C[rowbase + z1];
                for (int tb = rs; tb < re; tb += 32) {
                    const int t = tb + lane;
                    float d2; int idx;
                    if (t < re) {
                        const float4 c = P[t];
                        idx = __float_as_int(c.w);
                        const float sqm = c.x * c.x + c.y * c.y + c.z * c.z;
                        const float dot = fmaf(qx, c.x, fmaf(qy, c.y, qz * c.z));
                        d2 = fmaf(-2.0f, dot, sqn + sqm);
                        if (idx == qn) { d2 = CUDART_INF_F; idx = 0x7fffffff; }
                    } else {
                        d2 = CUDART_INF_F; idx = 0x7fffffff;
                    }
                    unsigned mask = __ballot_sync(FULL,
                        (d2 < thr) || (d2 == thr && idx < thri));
                    while (mask) {
                        const int   src = __ffs(mask) - 1;
                        const float v   = __shfl_sync(FULL, d2,  src);
                        const int   vi  = __shfl_sync(FULL, idx, src);
                        insert_lex(v, vi, lane, kd, ki, thr, thri);
                        mask &= mask - 1;
                    }
                }
            }
        }

        // stopping guarantee: any unexamined point is geometrically outside the
        // region box; its d2 >= dmin^2 (faces at grid edge contribute INF since
        // out-of-range points were clamped INWARD -> physically beyond that
        // face only if the face is at the grid edge, i.e. inside the region).
        const bool full = (x0 == 0 && x1 == G - 1 && y0 == 0 && y1 == G - 1 &&
                           z0 == 0 && z1 == G - 1);
        if (full) break;
        const float kd15 = __shfl_sync(FULL, kd, KNN - 1);
        float dmin = CUDART_INF_F;
        if (x0 > 0)     dmin = fminf(dmin, qx - (XMIN + x0 * Hc));
        if (x1 < G - 1) dmin = fminf(dmin, (XMIN + (x1 + 1) * Hc) - qx);
        if (y0 > 0)     dmin = fminf(dmin, qy - (XMIN + y0 * Hc));
        if (y1 < G - 1) dmin = fminf(dmin, (XMIN + (y1 + 1) * Hc) - qy);
        if (z0 > 0)     dmin = fminf(dmin, qz - (XMIN + z0 * Hc));
        if (z1 < G - 1) dmin = fminf(dmin, (XMIN + (z1 + 1) * Hc) - qz);
        if (kd15 + 1e-4f < dmin * dmin) break;   // 1e-4 >> d2 rounding error
    }

    // ---- Edge lengths + L1: lanes 0..15 each handle one neighbor ----
    const float pqx = pp[qn * 3 + 0];
    const float pqy = pp[qn * 3 + 1];
    const float pqz = pp[qn * 3 + 2];

    float partial = 0.0f;
    if (lane < KNN) {
        const int nb = ki;
        float rx = pr[nb * 3 + 0] - qx;
        float ry = pr[nb * 3 + 1] - qy;
        float rz = pr[nb * 3 + 2] - qz;
        float dref = sqrtf(rx * rx + ry * ry + rz * rz);
        float px = pp[nb * 3 + 0] - pqx;
        float py = pp[nb * 3 + 1] - pqy;
        float pz = pp[nb * 3 + 2] - pqz;
        float dprd = sqrtf(px * px + py * py + pz * pz);
        partial = fabsf(dref - dprd);
    }

    // Deterministic warp + block reduction
#pragma unroll
    for (int o = 16; o > 0; o >>= 1)
        partial += __shfl_xor_sync(FULL, partial, o);
    if (lane == 0) wsum[wid] = partial;
    __syncthreads();

    if (wid == 0) {
        float s = (lane < WPB) ? wsum[lane] : 0.0f;
#pragma unroll
        for (int o = 16; o > 0; o >>= 1)
            s += __shfl_xor_sync(FULL, s, o);
        if (lane == 0) g_partials[blockIdx.x] = s;
    }
}

__global__ void finalize_kernel(float* __restrict__ out)
{
    __shared__ double sred[256];
    int t = threadIdx.x;
    double s = 0.0;
    for (int i = t; i < NBLK; i += 256) s += (double)g_partials[i];
    sred[t] = s;
    __syncthreads();
#pragma unroll
    for (int st = 128; st > 0; st >>= 1) {
        if (t < st) sred[t] += sred[t + st];
        __syncthreads();
    }
    if (t == 0) out[0] = (float)(sred[0] / TOTAL_EDGES);
}

extern "C" void kernel_launch(void* const* d_in, const int* in_sizes, int n_in,
                              void* d_out, int out_size)
{
    (void)in_sizes; (void)n_in; (void)out_size;
    const float* points_ref = (const float*)d_in[0];
    const float* points     = (const float*)d_in[1];
    zero_kernel<<<138, 256>>>();
    count_kernel<<<64, 256>>>(points_ref);
    scan_kernel<<<2, 1024>>>();
    scatter_kernel<<<64, 256>>>(points_ref);
    knn_loss_kernel<<<NBLK, KBLOCK>>>(points_ref, points);
    finalize_kernel<<<1, 256>>>((float*)d_out);
}

// round 16
// speedup vs baseline: 1.0312x; 1.0312x over previous
#include <cuda_runtime.h>
#include <math_constants.h>

// Problem constants
#define BQ    2
#define NQ    8192
#define KNN   16
#define FULL  0xffffffffu
#define TOTAL_EDGES ((double)(BQ) * (double)(NQ) * (double)(KNN))

// Grid
#define G     26
#define NC    (G * G * G)          // 17576 cells per batch
#define NCB   (2 * NC)
#define Hc    0.4f
#define INVH  2.5f
#define XMIN  (-5.2f)              // XMIN + G*Hc = +5.2 (out-of-range clamped inward)

// KNN kernel layout
#define WPB   8
#define KBLOCK 256
#define NBLK  ((BQ * NQ) / WPB)    // 2048 blocks, 1 query per warp

__device__ int    g_counts[NCB];
__device__ int    g_cursor[NCB];
__device__ int    g_starts[NCB];          // per-batch exclusive prefix of counts
__device__ float4 g_pts[BQ * NQ];         // (x, y, z, idx-as-int-bits), cell-ordered
__device__ float  g_partials[NBLK];

__device__ __forceinline__ int cell_of(float x) {
    int c = (int)floorf((x - XMIN) * INVH);
    return min(max(c, 0), G - 1);
}

// ---------------- build kernels ----------------
__global__ void zero_kernel()
{
    for (int i = blockIdx.x * blockDim.x + threadIdx.x; i < NCB;
         i += gridDim.x * blockDim.x) {
        g_counts[i] = 0;
        g_cursor[i] = 0;
    }
}

__global__ void count_kernel(const float* __restrict__ pr)
{
    int gid = blockIdx.x * blockDim.x + threadIdx.x;
    if (gid >= BQ * NQ) return;
    int b = gid >> 13;                // / NQ
    float x = pr[gid * 3 + 0];
    float y = pr[gid * 3 + 1];
    float z = pr[gid * 3 + 2];
    int cell = (cell_of(x) * G + cell_of(y)) * G + cell_of(z);
    atomicAdd(&g_counts[b * NC + cell], 1);
}

// Exclusive prefix sum per batch (blockIdx.x = batch). 1024 threads.
__global__ void scan_kernel()
{
    __shared__ int warpsum[32];
    __shared__ int carry_s;
    const int base = blockIdx.x * NC;
    const int tid  = threadIdx.x;
    const int wid  = tid >> 5;
    const int lane = tid & 31;
    if (tid == 0) carry_s = 0;
    __syncthreads();

    const int nchunk = (NC + 1023) / 1024;
    for (int c = 0; c < nchunk; ++c) {
        int i = c * 1024 + tid;
        int v = (i < NC) ? g_counts[base + i] : 0;
        int x = v;
#pragma unroll
        for (int o = 1; o < 32; o <<= 1) {
            int t = __shfl_up_sync(FULL, x, o);
            if (lane >= o) x += t;
        }
        if (lane == 31) warpsum[wid] = x;
        __syncthreads();
        if (wid == 0) {
            int w = warpsum[lane];
#pragma unroll
            for (int o = 1; o < 32; o <<= 1) {
                int t = __shfl_up_sync(FULL, w, o);
                if (lane >= o) w += t;
            }
            warpsum[lane] = w;       // inclusive across warps
        }
        __syncthreads();
        int woff = (wid > 0) ? warpsum[wid - 1] : 0;
        if (i < NC) g_starts[base + i] = carry_s + woff + x - v;
        int total = warpsum[31];
        __syncthreads();
        if (tid == 0) carry_s += total;
        __syncthreads();
    }
}

__global__ void scatter_kernel(const float* __restrict__ pr)
{
    int gid = blockIdx.x * blockDim.x + threadIdx.x;
    if (gid >= BQ * NQ) return;
    int b = gid >> 13;
    int n = gid & (NQ - 1);
    float x = pr[gid * 3 + 0];
    float y = pr[gid * 3 + 1];
    float z = pr[gid * 3 + 2];
    int cell = (cell_of(x) * G + cell_of(y)) * G + cell_of(z);
    int pos  = b * NQ + g_starts[b * NC + cell] + atomicAdd(&g_cursor[b * NC + cell], 1);
    g_pts[pos] = make_float4(x, y, z, __int_as_float(n));
}

// ---------------- KNN + loss ----------------
// Lexicographic insert into warp-distributed sorted top-16 (lane l<16 holds
// the (l+1)-th smallest (d2, idx)). Order-independent: the final 16-set is the
// unique lex-minimal set, matching top_k (ascending d2, ties by lower index)
// regardless of candidate processing order. Each candidate is scanned exactly
// once (delta shells), so no duplicates ever enter.
__device__ __forceinline__ void insert_lex(float v, int vi, int lane,
                                           float& kd, int& ki,
                                           float& thr, int& thri)
{
    const unsigned le = __ballot_sync(FULL,
        (lane < KNN) && ((kd < v) || (kd == v && ki < vi)));
    const int pos = __popc(le);      // pos==16 -> no-op (stale entry)
    const float kdu = __shfl_up_sync(FULL, kd, 1);
    const int   kiu = __shfl_up_sync(FULL, ki, 1);
    if (lane >= pos) {
        kd = (lane == pos) ? v  : kdu;
        ki = (lane == pos) ? vi : kiu;
    }
    thr  = __shfl_sync(FULL, kd, KNN - 1);
    thri = __shfl_sync(FULL, ki, KNN - 1);
}

// Scan one z-segment [za, zb] of row `rowbase` (cell-ordered point range).
__device__ __forceinline__ void scan_seg(
    const float4* __restrict__ P, const int* __restrict__ S,
    const int* __restrict__ C, int rowbase, int za, int zb, int qn,
    float qx, float qy, float qz, float sqn, int lane,
    float& kd, int& ki, float& thr, int& thri)
{
    const int rs = S[rowbase + za];
    const int re = S[rowbase + zb] + C[rowbase + zb];
    for (int tb = rs; tb < re; tb += 32) {
        const int t = tb + lane;
        float d2 = CUDART_INF_F;
        int   idx = 0x7fffffff;
        if (t < re) {
            const float4 c = P[t];
            idx = __float_as_int(c.w);
            const float sqm = c.x * c.x + c.y * c.y + c.z * c.z;
            const float dot = fmaf(qx, c.x, fmaf(qy, c.y, qz * c.z));
            d2 = fmaf(-2.0f, dot, sqn + sqm);       // sq_n + sq_m - 2*dot
            if (idx == qn) { d2 = CUDART_INF_F; idx = 0x7fffffff; }
        }
        unsigned mask = __ballot_sync(FULL,
            (d2 < thr) || (d2 == thr && idx < thri));
        while (mask) {
            const int   src = __ffs(mask) - 1;
            const float v   = __shfl_sync(FULL, d2,  src);
            const int   vi  = __shfl_sync(FULL, idx, src);
            insert_lex(v, vi, lane, kd, ki, thr, thri);
            mask &= mask - 1;
        }
    }
}

__global__ __launch_bounds__(KBLOCK)
void knn_loss_kernel(const float* __restrict__ points_ref,
                     const float* __restrict__ points)
{
    __shared__ float wsum[WPB];
    const int tid  = threadIdx.x;
    const int wid  = tid >> 5;
    const int lane = tid & 31;
    const int qg   = blockIdx.x * WPB + wid;      // global query id
    const int b    = qg >> 13;
    const int qn   = qg & (NQ - 1);

    const float* __restrict__ pr = points_ref + (size_t)b * NQ * 3;
    const float* __restrict__ pp = points     + (size_t)b * NQ * 3;
    const float4* __restrict__ P = g_pts + (size_t)b * NQ;
    const int* __restrict__ S = g_starts + b * NC;
    const int* __restrict__ C = g_counts + b * NC;

    const float qx  = pr[qn * 3 + 0];
    const float qy  = pr[qn * 3 + 1];
    const float qz  = pr[qn * 3 + 2];
    const float sqn = qx * qx + qy * qy + qz * qz;

    const int ccx = cell_of(qx), ccy = cell_of(qy), ccz = cell_of(qz);

    float kd  = CUDART_INF_F;  int ki   = 0x7fffffff;
    float thr = CUDART_INF_F;  int thri = (int)0x80000000;  // no eq-admit vs INF

    // ---- ring 1: full 3x3x3 (clamped) box ----
    int x0 = max(ccx - 1, 0), x1 = min(ccx + 1, G - 1);
    int y0 = max(ccy - 1, 0), y1 = min(ccy + 1, G - 1);
    int z0 = max(ccz - 1, 0), z1 = min(ccz + 1, G - 1);
    for (int cx = x0; cx <= x1; ++cx)
        for (int cy = y0; cy <= y1; ++cy)
            scan_seg(P, S, C, (cx * G + cy) * G, z0, z1, qn,
                     qx, qy, qz, sqn, lane, kd, ki, thr, thri);

    // ---- ring expansion: scan ONLY the new shell (each candidate once) ----
    for (int ring = 2;; ++ring) {
        const bool full = (x0 == 0 && x1 == G - 1 && y0 == 0 && y1 == G - 1 &&
                           z0 == 0 && z1 == G - 1);
        if (full) break;
        // Stop bound: any unexamined point lies outside the current box, so its
        // d2 >= dmin^2 (faces at the grid edge contribute INF: out-of-range
        // points were clamped INWARD, hence already inside scanned cells).
        const float kd15 = __shfl_sync(FULL, kd, KNN - 1);
        float dmin = CUDART_INF_F;
        if (x0 > 0)     dmin = fminf(dmin, qx - (XMIN + x0 * Hc));
        if (x1 < G - 1) dmin = fminf(dmin, (XMIN + (x1 + 1) * Hc) - qx);
        if (y0 > 0)     dmin = fminf(dmin, qy - (XMIN + y0 * Hc));
        if (y1 < G - 1) dmin = fminf(dmin, (XMIN + (y1 + 1) * Hc) - qy);
        if (z0 > 0)     dmin = fminf(dmin, qz - (XMIN + z0 * Hc));
        if (z1 < G - 1) dmin = fminf(dmin, (XMIN + (z1 + 1) * Hc) - qz);
        if (kd15 + 1e-4f < dmin * dmin) break;   // 1e-4 >> d2 rounding error

        const int nx0 = max(ccx - ring, 0), nx1 = min(ccx + ring, G - 1);
        const int ny0 = max(ccy - ring, 0), ny1 = min(ccy + ring, G - 1);
        const int nz0 = max(ccz - ring, 0), nz1 = min(ccz + ring, G - 1);
        for (int cx = nx0; cx <= nx1; ++cx) {
            for (int cy = ny0; cy <= ny1; ++cy) {
                const int rowbase = (cx * G + cy) * G;
                const bool inPrev = (cx >= x0 && cx <= x1 && cy >= y0 && cy <= y1);
                if (inPrev) {
                    if (nz0 < z0) scan_seg(P, S, C, rowbase, nz0, z0 - 1, qn,
                                           qx, qy, qz, sqn, lane, kd, ki, thr, thri);
                    if (nz1 > z1) scan_seg(P, S, C, rowbase, z1 + 1, nz1, qn,
                                           qx, qy, qz, sqn, lane, kd, ki, thr, thri);
                } else {
                    scan_seg(P, S, C, rowbase, nz0, nz1, qn,
                             qx, qy, qz, sqn, lane, kd, ki, thr, thri);
                }
            }
        }
        x0 = nx0; x1 = nx1; y0 = ny0; y1 = ny1; z0 = nz0; z1 = nz1;
    }

    // ---- Edge lengths + L1: lanes 0..15 each handle one neighbor ----
    const float pqx = pp[qn * 3 + 0];
    const float pqy = pp[qn * 3 + 1];
    const float pqz = pp[qn * 3 + 2];

    float partial = 0.0f;
    if (lane < KNN) {
        const int nb = ki;
        float rx = pr[nb * 3 + 0] - qx;
        float ry = pr[nb * 3 + 1] - qy;
        float rz = pr[nb * 3 + 2] - qz;
        float dref = sqrtf(rx * rx + ry * ry + rz * rz);
        float px = pp[nb * 3 + 0] - pqx;
        float py = pp[nb * 3 + 1] - pqy;
        float pz = pp[nb * 3 + 2] - pqz;
        float dprd = sqrtf(px * px + py * py + pz * pz);
        partial = fabsf(dref - dprd);
    }

    // Deterministic warp + block reduction
#pragma unroll
    for (int o = 16; o > 0; o >>= 1)
        partial += __shfl_xor_sync(FULL, partial, o);
    if (lane == 0) wsum[wid] = partial;
    __syncthreads();

    if (wid == 0) {
        float s = (lane < WPB) ? wsum[lane] : 0.0f;
#pragma unroll
        for (int o = 16; o > 0; o >>= 1)
            s += __shfl_xor_sync(FULL, s, o);
        if (lane == 0) g_partials[blockIdx.x] = s;
    }
}

__global__ void finalize_kernel(float* __restrict__ out)
{
    __shared__ double sred[256];
    int t = threadIdx.x;
    double s = 0.0;
    for (int i = t; i < NBLK; i += 256) s += (double)g_partials[i];
    sred[t] = s;
    __syncthreads();
#pragma unroll
    for (int st = 128; st > 0; st >>= 1) {
        if (t < st) sred[t] += sred[t + st];
        __syncthreads();
    }
    if (t == 0) out[0] = (float)(sred[0] / TOTAL_EDGES);
}

extern "C" void kernel_launch(void* const* d_in, const int* in_sizes, int n_in,
                              void* d_out, int out_size)
{
    (void)in_sizes; (void)n_in; (void)out_size;
    const float* points_ref = (const float*)d_in[0];
    const float* points     = (const float*)d_in[1];
    zero_kernel<<<138, 256>>>();
    count_kernel<<<64, 256>>>(points_ref);
    scan_kernel<<<2, 1024>>>();
    scatter_kernel<<<64, 256>>>(points_ref);
    knn_loss_kernel<<<NBLK, KBLOCK>>>(points_ref, points);
    finalize_kernel<<<1, 256>>>((float*)d_out);
}